// round 3
// baseline (speedup 1.0000x reference)
#include <cuda_runtime.h>
#include <cuda_fp16.h>
#include <math.h>
#include <stdint.h>

// ============================================================================
// Problem constants
// ============================================================================
#define NKINDS   8
#define DMODEL   256
#define MAXT     65536
#define TILE_M   128
#define MAX_TILES 520

// Padded K strides (halves) for conflict-free ldmatrix (stride % 128B == 16B)
#define W1_KS    72     // K=48 padded
#define W2_KS    264    // K=256 padded
#define W1_BYTES (256 * W1_KS * 2)    // 36864
#define W2_BYTES (256 * W2_KS * 2)    // 135168

// smem layout (bytes)
#define SM_TOK   0                     // 128 ints
#define SM_BM    512                   // 24 floats
#define SM_FF    640                   // 128 x 72 halves = 18432
#define SM_HS    19584                 // 128 x 264 halves = 67584
#define SM_W1    19584                 // aliases HS (36864 <= 67584)
#define SM_W2    (19584 + 67584)       // 87168, size 135168
#define SMEM_BYTES (SM_W2 + W2_BYTES)  // 222336

// ============================================================================
// Device scratch
// ============================================================================
__device__ int   g_counts[NKINDS];
__device__ int   g_idx[NKINDS * MAXT];
__device__ __align__(1024) unsigned char g_W1T[NKINDS * W1_BYTES];
__device__ __align__(1024) unsigned char g_W2T[NKINDS * W2_BYTES];
__device__ float g_bias2[NKINDS * DMODEL];
__device__ int   g_work[MAX_TILES];
__device__ int   g_ntiles;

// ============================================================================
// Baseline-ISA helpers (sm_80-era: ldmatrix / mma.sync / cp.async)
// ============================================================================
__device__ __forceinline__ uint32_t smem_u32(const void* p) {
    uint32_t a;
    asm("{ .reg .u64 t; cvta.to.shared.u64 t, %1; cvt.u32.u64 %0, t; }" : "=r"(a) : "l"(p));
    return a;
}

__device__ __forceinline__ void ldsm_x4(uint32_t r[4], uint32_t addr) {
    asm volatile("ldmatrix.sync.aligned.m8n8.x4.shared.b16 {%0,%1,%2,%3}, [%4];"
        : "=r"(r[0]), "=r"(r[1]), "=r"(r[2]), "=r"(r[3]) : "r"(addr));
}

__device__ __forceinline__ void mma16816(float c[4], const uint32_t a[4], const uint32_t* b) {
    asm volatile(
        "mma.sync.aligned.m16n8k16.row.col.f32.f16.f16.f32 "
        "{%0,%1,%2,%3}, {%4,%5,%6,%7}, {%8,%9}, {%0,%1,%2,%3};"
        : "+f"(c[0]), "+f"(c[1]), "+f"(c[2]), "+f"(c[3])
        : "r"(a[0]), "r"(a[1]), "r"(a[2]), "r"(a[3]), "r"(b[0]), "r"(b[1]));
}

__device__ __forceinline__ void cp16(uint32_t saddr, const void* gaddr) {
    asm volatile("cp.async.cg.shared.global [%0], [%1], 16;" :: "r"(saddr), "l"(gaddr));
}
#define CP_COMMIT() asm volatile("cp.async.commit_group;" ::: "memory")
#define CP_WAIT(n)  asm volatile("cp.async.wait_group %0;" :: "n"(n) : "memory")

// A-fragment address (row-major tile, 16x16): lane l -> tile t = l>>3, r = l&7
//   row = m0 + r + (t&1)*8, col = kb + (t>>1)*8
__device__ __forceinline__ uint32_t a_addr(uint32_t base, int strideH, int m0, int kb, int lane) {
    int t = lane >> 3, r = lane & 7;
    int row = m0 + r + (t & 1) * 8;
    int col = kb + (t >> 1) * 8;
    return base + (uint32_t)(row * strideH + col) * 2u;
}

// B-fragment x4 (two adjacent n8 blocks): tile t: row = n0 + (t>>1)*8 + r, col = kb + (t&1)*8
//   regs: {b0_blk0, b1_blk0, b0_blk1, b1_blk1}
__device__ __forceinline__ uint32_t b_addr(uint32_t base, int strideH, int n0, int kb, int lane) {
    int t = lane >> 3, r = lane & 7;
    int row = n0 + (t >> 1) * 8 + r;
    int col = kb + (t & 1) * 8;
    return base + (uint32_t)(row * strideH + col) * 2u;
}

__device__ __forceinline__ float gelu_exact(float x) {
    return 0.5f * x * (1.0f + erff(x * 0.7071067811865476f));
}

__device__ __forceinline__ uint32_t pack2(float lo, float hi) {
    __half2 h = __floats2half2_rn(lo, hi);
    return *reinterpret_cast<uint32_t*>(&h);
}

// ============================================================================
// Kernel 1: weight prep — fp16 [N][K] padded-row transposes; fold b2+kemb
// ============================================================================
__global__ void prep_kernel(const float* __restrict__ W1, const float* __restrict__ W2,
                            const float* __restrict__ b2, const float* __restrict__ kemb) {
    int idx = blockIdx.x * blockDim.x + threadIdx.x;
    // W2T[k][n][j] = W2[k][j][n], j in [0,264), pad j>=256 with 0
    if (idx < NKINDS * 256 * W2_KS) {
        int k = idx / (256 * W2_KS);
        int r = idx - k * (256 * W2_KS);
        int n = r / W2_KS;
        int j = r - n * W2_KS;
        float v = (j < 256) ? W2[(size_t)k * 65536 + j * 256 + n] : 0.0f;
        reinterpret_cast<__half*>(g_W2T)[(size_t)k * 256 * W2_KS + n * W2_KS + j] = __float2half(v);
    }
    // W1T[k][n][j] = W1[k][j][n], j in [0,72), pad j>=48 with 0
    if (idx < NKINDS * 256 * W1_KS) {
        int k = idx / (256 * W1_KS);
        int r = idx - k * (256 * W1_KS);
        int n = r / W1_KS;
        int j = r - n * W1_KS;
        float v = (j < 48) ? W1[(size_t)k * 48 * 256 + j * 256 + n] : 0.0f;
        reinterpret_cast<__half*>(g_W1T)[(size_t)k * 256 * W1_KS + n * W1_KS + j] = __float2half(v);
    }
    if (idx < NKINDS * DMODEL) g_bias2[idx] = b2[idx] + kemb[idx];
    if (idx < NKINDS) g_counts[idx] = 0;
}

// ============================================================================
// Kernel 2: bucket tokens by kind
// ============================================================================
__global__ void bucket_kernel(const int* __restrict__ kinds, int T) {
    __shared__ int s_cnt[NKINDS];
    __shared__ int s_base[NKINDS];
    int tid = threadIdx.x;
    if (tid < NKINDS) s_cnt[tid] = 0;
    __syncthreads();
    int t = blockIdx.x * blockDim.x + tid;
    int k = 0, pos = 0;
    bool ok = (t < T);
    if (ok) {
        k = kinds[t];
        pos = atomicAdd(&s_cnt[k], 1);
    }
    __syncthreads();
    if (tid < NKINDS) s_base[tid] = atomicAdd(&g_counts[tid], s_cnt[tid]);
    __syncthreads();
    if (ok) g_idx[k * MAXT + s_base[k] + pos] = t;
}

// ============================================================================
// Kernel 3: (kind, tile) work list
// ============================================================================
__global__ void schedule_kernel() {
    if (threadIdx.x == 0) {
        int t = 0;
        for (int k = 0; k < NKINDS; k++) {
            int nt = (g_counts[k] + TILE_M - 1) >> 7;
            for (int i = 0; i < nt; i++) g_work[t++] = (k << 16) | i;
        }
        g_ntiles = t;
    }
}

// ============================================================================
// Kernel 4: fused grouped MLP via mma.sync (HMMA), 256 threads / 8 warps
// ============================================================================
__global__ void __launch_bounds__(256, 1) fused_kernel(
    const float* __restrict__ values, const float* __restrict__ Bmat,
    const float* __restrict__ b1, float* __restrict__ out) {

    int b = blockIdx.x;
    if (b >= g_ntiles) return;
    int w = g_work[b];
    int k = w >> 16;
    int tile = w & 0xFFFF;
    int cnt = g_counts[k];

    extern __shared__ unsigned char smem[];
    uint32_t sb = smem_u32(smem);
    int tid = threadIdx.x;
    int warp = tid >> 5;
    int lane = tid & 31;
    int m0 = warp * 16;

    int* s_tok = reinterpret_cast<int*>(smem + SM_TOK);
    float* s_bm = reinterpret_cast<float*>(smem + SM_BM);

    // ---- async weight loads: W1T (group 1 deep), then W2T ----
    {
        const unsigned char* g1 = g_W1T + (size_t)k * W1_BYTES;
        uint32_t d1 = sb + SM_W1;
#pragma unroll
        for (int i = 0; i < 9; i++) {           // 9*256*16 = 36864
            int off = (tid + 256 * i) * 16;
            cp16(d1 + off, g1 + off);
        }
        CP_COMMIT();
        const unsigned char* g2 = g_W2T + (size_t)k * W2_BYTES;
        uint32_t d2 = sb + SM_W2;
#pragma unroll
        for (int i = 0; i < 33; i++) {          // 33*256*16 = 135168
            int off = (tid + 256 * i) * 16;
            cp16(d2 + off, g2 + off);
        }
        CP_COMMIT();
    }

    if (tid < 24) s_bm[tid] = Bmat[tid];
    if (tid < TILE_M) {
        int slot = tile * TILE_M + tid;
        s_tok[tid] = (slot < cnt) ? g_idx[k * MAXT + slot] : -1;
    }
    __syncthreads();

    // ---- Fourier features -> smem ff (threads 0..127, one token each) ----
    if (tid < TILE_M) {
        int tok = s_tok[tid];
        float v = (tok >= 0) ? values[tok] : 0.0f;
        float tp = 6.283185307179586f * v;
        __half* row = reinterpret_cast<__half*>(smem + SM_FF) + tid * W1_KS;
#pragma unroll
        for (int j = 0; j < 24; j++) {
            float s, c;
            sincosf(tp * s_bm[j], &s, &c);
            row[j]      = __float2half(s);
            row[24 + j] = __float2half(c);
        }
    }
    CP_WAIT(1);           // W1T arrived
    __syncthreads();      // ff + W1T visible

    // ---- GEMM1: D1[128,256] = ff[128,48] @ W1T^T  (K = 48, 3 k-steps) ----
    float acc1[32][4];
#pragma unroll
    for (int i = 0; i < 32; i++)
#pragma unroll
        for (int j = 0; j < 4; j++) acc1[i][j] = 0.0f;

#pragma unroll
    for (int k16 = 0; k16 < 3; k16++) {
        int kb = k16 * 16;
        uint32_t a[4];
        ldsm_x4(a, a_addr(sb + SM_FF, W1_KS, m0, kb, lane));
#pragma unroll
        for (int nb = 0; nb < 16; nb++) {
            uint32_t bf[4];
            ldsm_x4(bf, b_addr(sb + SM_W1, W1_KS, nb * 16, kb, lane));
            mma16816(acc1[2 * nb],     a, bf);
            mma16816(acc1[2 * nb + 1], a, bf + 2);
        }
    }
    __syncthreads();      // all W1T reads done before Hs overwrites the alias

    // ---- epilogue 1: +b1, exact GELU, fp16 -> Hs ----
    {
        const float* b1k = b1 + k * DMODEL;
        int r0 = m0 + (lane >> 2);
        int r1 = r0 + 8;
        int c0 = (lane & 3) * 2;
        __half* hs = reinterpret_cast<__half*>(smem + SM_HS);
#pragma unroll
        for (int n8 = 0; n8 < 32; n8++) {
            int col = n8 * 8 + c0;
            float bi0 = b1k[col], bi1 = b1k[col + 1];
            uint32_t p0 = pack2(gelu_exact(acc1[n8][0] + bi0), gelu_exact(acc1[n8][1] + bi1));
            uint32_t p1 = pack2(gelu_exact(acc1[n8][2] + bi0), gelu_exact(acc1[n8][3] + bi1));
            *reinterpret_cast<uint32_t*>(hs + r0 * W2_KS + col) = p0;
            *reinterpret_cast<uint32_t*>(hs + r1 * W2_KS + col) = p1;
        }
    }
    CP_WAIT(0);           // W2T arrived
    __syncthreads();      // Hs + W2T visible

    // ---- GEMM2: D2[128,256] = Hs[128,256] @ W2T^T, in two N-halves ----
    const float* b2k = g_bias2 + k * DMODEL;
    int r0 = m0 + (lane >> 2);
    int r1 = r0 + 8;
    int c0 = (lane & 3) * 2;
    int tok0 = s_tok[r0];
    int tok1 = s_tok[r1];
    float* o0 = out + (size_t)(tok0 < 0 ? 0 : tok0) * DMODEL;
    float* o1 = out + (size_t)(tok1 < 0 ? 0 : tok1) * DMODEL;

#pragma unroll 1
    for (int nh = 0; nh < 2; nh++) {
        float acc[16][4];
#pragma unroll
        for (int i = 0; i < 16; i++)
#pragma unroll
            for (int j = 0; j < 4; j++) acc[i][j] = 0.0f;

#pragma unroll 1
        for (int k16 = 0; k16 < 16; k16++) {
            int kb = k16 * 16;
            uint32_t a[4];
            ldsm_x4(a, a_addr(sb + SM_HS, W2_KS, m0, kb, lane));
#pragma unroll
            for (int nb = 0; nb < 8; nb++) {
                uint32_t bf[4];
                ldsm_x4(bf, b_addr(sb + SM_W2, W2_KS, nh * 128 + nb * 16, kb, lane));
                mma16816(acc[2 * nb],     a, bf);
                mma16816(acc[2 * nb + 1], a, bf + 2);
            }
        }

        // epilogue 2: + (b2 + kind_emb), scatter float2 pairs to token rows
#pragma unroll
        for (int n8 = 0; n8 < 16; n8++) {
            int col = nh * 128 + n8 * 8 + c0;
            float bi0 = b2k[col], bi1 = b2k[col + 1];
            if (tok0 >= 0) {
                float2 v0 = make_float2(acc[n8][0] + bi0, acc[n8][1] + bi1);
                *reinterpret_cast<float2*>(o0 + col) = v0;
            }
            if (tok1 >= 0) {
                float2 v1 = make_float2(acc[n8][2] + bi0, acc[n8][3] + bi1);
                *reinterpret_cast<float2*>(o1 + col) = v1;
            }
        }
    }
}

// ============================================================================
// kernel_launch — graph-capturable, allocation-free
// ============================================================================
extern "C" void kernel_launch(void* const* d_in, const int* in_sizes, int n_in,
                              void* d_out, int out_size) {
    const float* values = (const float*)d_in[0];
    const int*   kinds  = (const int*)d_in[1];
    const float* Bmat   = (const float*)d_in[2];
    const float* kemb   = (const float*)d_in[3];
    const float* W1     = (const float*)d_in[4];
    const float* b1     = (const float*)d_in[5];
    const float* W2     = (const float*)d_in[6];
    const float* b2     = (const float*)d_in[7];
    float* out = (float*)d_out;
    int T = in_sizes[1];

    static int smem_set = 0;
    if (!smem_set) {
        cudaFuncSetAttribute(fused_kernel, cudaFuncAttributeMaxDynamicSharedMemorySize, SMEM_BYTES);
        smem_set = 1;
    }

    int prep_elems = NKINDS * 256 * W2_KS;
    prep_kernel<<<(prep_elems + 255) / 256, 256>>>(W1, W2, b2, kemb);
    bucket_kernel<<<(T + 255) / 256, 256>>>(kinds, T);
    schedule_kernel<<<1, 32>>>();
    fused_kernel<<<MAX_TILES, 256, SMEM_BYTES>>>(values, Bmat, b1, out);
}

// round 4
// speedup vs baseline: 1.3052x; 1.3052x over previous
#include <cuda_runtime.h>
#include <cuda_fp16.h>
#include <math.h>
#include <stdint.h>

// ============================================================================
// Problem constants
// ============================================================================
#define NKINDS   8
#define DMODEL   256
#define MAXT     65536
#define TILE_M   128
#define MAX_TILES 520

// Padded K strides (halves): stride % 64 halves == 8 -> conflict-free ldmatrix
#define W1_KS    72     // K=48 padded
#define W2_KS    264    // K=256 padded
#define W1_BYTES (256 * W1_KS * 2)    // 36864
#define W2_BYTES (256 * W2_KS * 2)    // 135168

// smem layout (bytes)
#define SM_TOK   0                     // 128 ints
#define SM_BM    512                   // 24 floats
#define SM_BAR1  608                   // mbarrier (8B)
#define SM_BAR2  616                   // mbarrier (8B)
#define SM_FF    640                   // 128 x 72 halves = 18432
#define SM_HS    19584                 // 128 x 264 halves = 67584 (W1 aliases here)
#define SM_W1    19584
#define SM_W2    (19584 + 67584)       // 87168, size 135168
#define SMEM_BYTES (SM_W2 + W2_BYTES)  // 222336

// ============================================================================
// Device scratch
// ============================================================================
__device__ int   g_counts[NKINDS];
__device__ int   g_idx[NKINDS * MAXT];
__device__ __align__(1024) unsigned char g_W1T[NKINDS * W1_BYTES];
__device__ __align__(1024) unsigned char g_W2T[NKINDS * W2_BYTES];
__device__ float g_bias2[NKINDS * DMODEL];
__device__ int   g_work[MAX_TILES];
__device__ int   g_ntiles;

// ============================================================================
// PTX helpers (all plain sm_90-baseline features; no 'a'-suffix ISA)
// ============================================================================
__device__ __forceinline__ uint32_t smem_u32(const void* p) {
    uint32_t a;
    asm("{ .reg .u64 t; cvta.to.shared.u64 t, %1; cvt.u32.u64 %0, t; }" : "=r"(a) : "l"(p));
    return a;
}

__device__ __forceinline__ void ldsm_x4(uint32_t r[4], uint32_t addr) {
    asm volatile("ldmatrix.sync.aligned.m8n8.x4.shared.b16 {%0,%1,%2,%3}, [%4];"
        : "=r"(r[0]), "=r"(r[1]), "=r"(r[2]), "=r"(r[3]) : "r"(addr));
}

__device__ __forceinline__ void mma16816(float c[4], const uint32_t a[4], const uint32_t* b) {
    asm volatile(
        "mma.sync.aligned.m16n8k16.row.col.f32.f16.f16.f32 "
        "{%0,%1,%2,%3}, {%4,%5,%6,%7}, {%8,%9}, {%0,%1,%2,%3};"
        : "+f"(c[0]), "+f"(c[1]), "+f"(c[2]), "+f"(c[3])
        : "r"(a[0]), "r"(a[1]), "r"(a[2]), "r"(a[3]), "r"(b[0]), "r"(b[1]));
}

__device__ __forceinline__ void bulk_cp(uint32_t dst, const void* src, uint32_t bytes, uint32_t mbar) {
    asm volatile(
        "cp.async.bulk.shared::cluster.global.mbarrier::complete_tx::bytes [%0], [%1], %2, [%3];"
        :: "r"(dst), "l"(src), "r"(bytes), "r"(mbar) : "memory");
}

#define MBARRIER_INIT(a, c) \
    asm volatile("mbarrier.init.shared.b64 [%0], %1;" :: "r"((uint32_t)(a)), "r"((uint32_t)(c)) : "memory")
#define MBARRIER_EXPECT_TX(a, tx) \
    asm volatile("mbarrier.arrive.expect_tx.shared.b64 _, [%0], %1;" :: "r"((uint32_t)(a)), "r"((uint32_t)(tx)) : "memory")
#define FENCE_PROXY_ASYNC() asm volatile("fence.proxy.async.shared::cta;" ::: "memory")

#define MBARRIER_WAIT_PARITY(mbar_addr, phase_parity) do { \
    uint32_t _mbar = (uint32_t)(mbar_addr); \
    uint32_t _parity = (uint32_t)(phase_parity); \
    uint32_t _done; \
    asm volatile( \
        "{\n\t.reg .pred p;\n\t" \
        "mbarrier.try_wait.parity.acquire.cta.shared::cta.b64 p, [%1], %2;\n\t" \
        "selp.b32 %0, 1, 0, p;\n\t}" \
        : "=r"(_done) : "r"(_mbar), "r"(_parity) : "memory"); \
    if (!_done) { \
        asm volatile( \
            "{\n\t.reg .pred P1;\n\t" \
            "WAIT_LOOP_%=:\n\t" \
            "mbarrier.try_wait.parity.acquire.cta.shared::cta.b64 P1, [%0], %1, 0x989680;\n\t" \
            "@P1 bra.uni WAIT_DONE_%=;\n\t" \
            "bra.uni WAIT_LOOP_%=;\n\t" \
            "WAIT_DONE_%=:\n\t}" \
            :: "r"(_mbar), "r"(_parity) : "memory"); \
    } \
} while (0)

__device__ __forceinline__ float gelu_exact(float x) {
    return 0.5f * x * (1.0f + erff(x * 0.7071067811865476f));
}

__device__ __forceinline__ uint32_t pack2(float lo, float hi) {
    __half2 h = __floats2half2_rn(lo, hi);
    return *reinterpret_cast<uint32_t*>(&h);
}

// ============================================================================
// Kernel 1: weight prep — fp16 [N][K] padded-row transposes; fold b2+kemb
// ============================================================================
__global__ void prep_kernel(const float* __restrict__ W1, const float* __restrict__ W2,
                            const float* __restrict__ b2, const float* __restrict__ kemb) {
    int idx = blockIdx.x * blockDim.x + threadIdx.x;
    if (idx < NKINDS * 256 * W2_KS) {
        int k = idx / (256 * W2_KS);
        int r = idx - k * (256 * W2_KS);
        int n = r / W2_KS;
        int j = r - n * W2_KS;
        float v = (j < 256) ? W2[(size_t)k * 65536 + j * 256 + n] : 0.0f;
        reinterpret_cast<__half*>(g_W2T)[(size_t)k * 256 * W2_KS + n * W2_KS + j] = __float2half(v);
    }
    if (idx < NKINDS * 256 * W1_KS) {
        int k = idx / (256 * W1_KS);
        int r = idx - k * (256 * W1_KS);
        int n = r / W1_KS;
        int j = r - n * W1_KS;
        float v = (j < 48) ? W1[(size_t)k * 48 * 256 + j * 256 + n] : 0.0f;
        reinterpret_cast<__half*>(g_W1T)[(size_t)k * 256 * W1_KS + n * W1_KS + j] = __float2half(v);
    }
    if (idx < NKINDS * DMODEL) g_bias2[idx] = b2[idx] + kemb[idx];
    if (idx < NKINDS) g_counts[idx] = 0;
}

// ============================================================================
// Kernel 2: bucket tokens by kind
// ============================================================================
__global__ void bucket_kernel(const int* __restrict__ kinds, int T) {
    __shared__ int s_cnt[NKINDS];
    __shared__ int s_base[NKINDS];
    int tid = threadIdx.x;
    if (tid < NKINDS) s_cnt[tid] = 0;
    __syncthreads();
    int t = blockIdx.x * blockDim.x + tid;
    int k = 0, pos = 0;
    bool ok = (t < T);
    if (ok) {
        k = kinds[t];
        pos = atomicAdd(&s_cnt[k], 1);
    }
    __syncthreads();
    if (tid < NKINDS) s_base[tid] = atomicAdd(&g_counts[tid], s_cnt[tid]);
    __syncthreads();
    if (ok) g_idx[k * MAXT + s_base[k] + pos] = t;
}

// ============================================================================
// Kernel 3: (kind, tile) work list (kind-major order)
// ============================================================================
__global__ void schedule_kernel() {
    if (threadIdx.x == 0) {
        int t = 0;
        for (int k = 0; k < NKINDS; k++) {
            int nt = (g_counts[k] + TILE_M - 1) >> 7;
            for (int i = 0; i < nt; i++) g_work[t++] = (k << 16) | i;
        }
        g_ntiles = t;
    }
}

// ============================================================================
// Kernel 4: persistent fused grouped MLP — HMMA, 64x64 warp tiles,
// bulk-copy weight staging with kind-reuse. 256 threads / 8 warps (2M x 4N).
// ============================================================================
__global__ void __launch_bounds__(256, 1) fused_kernel(
    const float* __restrict__ values, const float* __restrict__ Bmat,
    const float* __restrict__ b1, float* __restrict__ out) {

    extern __shared__ unsigned char smem[];
    uint32_t sb = smem_u32(smem);
    int tid = threadIdx.x;
    int warp = tid >> 5;
    int lane = tid & 31;
    int m0w = (warp >> 2) * 64;   // 2 M-groups of 64 rows
    int n0w = (warp & 3) * 64;    // 4 N-groups of 64 cols
    int t8 = lane >> 3, r8 = lane & 7;
    int rA = lane >> 2, cA = (lane & 3) * 2;

    int* s_tok = reinterpret_cast<int*>(smem + SM_TOK);
    float* s_bm = reinterpret_cast<float*>(smem + SM_BM);
    uint32_t bar1 = sb + SM_BAR1, bar2 = sb + SM_BAR2;

    if (tid == 0) { MBARRIER_INIT(bar1, 1); MBARRIER_INIT(bar2, 1); }
    if (tid < 24) s_bm[tid] = Bmat[tid];
    __syncthreads();

    int ntiles = g_ntiles;
    int start = (int)(((long long)ntiles * blockIdx.x) / gridDim.x);
    int end   = (int)(((long long)ntiles * (blockIdx.x + 1)) / gridDim.x);
    int prevk = -1;
    uint32_t par1 = 0, par2 = 0;

    for (int b = start; b < end; b++) {
        int w = g_work[b];
        int k = w >> 16;
        int tile = w & 0xFFFF;
        int cnt = g_counts[k];
        bool newk = (k != prevk);
        prevk = k;

        __syncthreads();   // previous tile's smem reads fully done
        if (tid == 0) {
            FENCE_PROXY_ASYNC();
            MBARRIER_EXPECT_TX(bar1, W1_BYTES);
            bulk_cp(sb + SM_W1, g_W1T + (size_t)k * W1_BYTES, W1_BYTES, bar1);
            if (newk) {
                MBARRIER_EXPECT_TX(bar2, W2_BYTES);
                bulk_cp(sb + SM_W2, g_W2T + (size_t)k * W2_BYTES, W2_BYTES, bar2);
            }
        }
        if (tid < TILE_M) {
            int slot = tile * TILE_M + tid;
            s_tok[tid] = (slot < cnt) ? g_idx[k * MAXT + slot] : -1;
        }
        __syncthreads();

        // ---- Fourier features: all 256 threads (128 rows x 2 band-halves) ----
        {
            int row = tid & 127;
            int j0 = (tid >> 7) * 12;
            int tok = s_tok[row];
            float v = (tok >= 0) ? values[tok] : 0.0f;
            float tp = 6.283185307179586f * v;
            __half* rp = reinterpret_cast<__half*>(smem + SM_FF) + row * W1_KS;
#pragma unroll
            for (int j = 0; j < 12; j++) {
                float s, c;
                sincosf(tp * s_bm[j0 + j], &s, &c);
                rp[j0 + j]      = __float2half(s);
                rp[24 + j0 + j] = __float2half(c);
            }
        }
        MBARRIER_WAIT_PARITY(bar1, par1);
        par1 ^= 1;
        __syncthreads();   // ff + W1 visible

        float acc[4][8][4];
#pragma unroll
        for (int i = 0; i < 4; i++)
#pragma unroll
            for (int j = 0; j < 8; j++)
#pragma unroll
                for (int q = 0; q < 4; q++) acc[i][j][q] = 0.0f;

        // ---- GEMM1: [128,256] = ff[128,48] @ W1^T (3 k-steps) ----
        {
            uint32_t aB[4], bB[4];
#pragma unroll
            for (int mt = 0; mt < 4; mt++)
                aB[mt] = sb + SM_FF + (uint32_t)((m0w + mt * 16 + r8 + (t8 & 1) * 8) * W1_KS + (t8 >> 1) * 8) * 2u;
#pragma unroll
            for (int nt = 0; nt < 4; nt++)
                bB[nt] = sb + SM_W1 + (uint32_t)((n0w + nt * 16 + (t8 >> 1) * 8 + r8) * W1_KS + (t8 & 1) * 8) * 2u;
#pragma unroll
            for (int kk = 0; kk < 3; kk++) {
                uint32_t af[4][4], bf[4][4];
#pragma unroll
                for (int mt = 0; mt < 4; mt++) ldsm_x4(af[mt], aB[mt] + kk * 32);
#pragma unroll
                for (int nt = 0; nt < 4; nt++) ldsm_x4(bf[nt], bB[nt] + kk * 32);
#pragma unroll
                for (int mt = 0; mt < 4; mt++)
#pragma unroll
                    for (int nt = 0; nt < 4; nt++) {
                        mma16816(acc[mt][2 * nt],     af[mt], bf[nt]);
                        mma16816(acc[mt][2 * nt + 1], af[mt], bf[nt] + 2);
                    }
            }
        }
        __syncthreads();   // W1 reads done; Hs region (alias) now writable

        // ---- epilogue 1: +b1, exact GELU, fp16 -> Hs ----
        {
            const float* b1k = b1 + k * DMODEL;
            __half* hs = reinterpret_cast<__half*>(smem + SM_HS);
#pragma unroll
            for (int mt = 0; mt < 4; mt++) {
                int r0 = m0w + mt * 16 + rA;
                int r1 = r0 + 8;
#pragma unroll
                for (int n8 = 0; n8 < 8; n8++) {
                    int col = n0w + n8 * 8 + cA;
                    float bi0 = b1k[col], bi1 = b1k[col + 1];
                    uint32_t p0 = pack2(gelu_exact(acc[mt][n8][0] + bi0), gelu_exact(acc[mt][n8][1] + bi1));
                    uint32_t p1 = pack2(gelu_exact(acc[mt][n8][2] + bi0), gelu_exact(acc[mt][n8][3] + bi1));
                    *reinterpret_cast<uint32_t*>(hs + r0 * W2_KS + col) = p0;
                    *reinterpret_cast<uint32_t*>(hs + r1 * W2_KS + col) = p1;
                }
            }
        }
        if (newk) { MBARRIER_WAIT_PARITY(bar2, par2); par2 ^= 1; }
        __syncthreads();   // Hs + W2 visible

        // ---- GEMM2: [128,256] = Hs[128,256] @ W2^T (16 k-steps, dbl-buffered) ----
#pragma unroll
        for (int i = 0; i < 4; i++)
#pragma unroll
            for (int j = 0; j < 8; j++)
#pragma unroll
                for (int q = 0; q < 4; q++) acc[i][j][q] = 0.0f;
        {
            uint32_t aB[4], bB[4];
#pragma unroll
            for (int mt = 0; mt < 4; mt++)
                aB[mt] = sb + SM_HS + (uint32_t)((m0w + mt * 16 + r8 + (t8 & 1) * 8) * W2_KS + (t8 >> 1) * 8) * 2u;
#pragma unroll
            for (int nt = 0; nt < 4; nt++)
                bB[nt] = sb + SM_W2 + (uint32_t)((n0w + nt * 16 + (t8 >> 1) * 8 + r8) * W2_KS + (t8 & 1) * 8) * 2u;

            uint32_t af0[4][4], bf0[4][4], af1[4][4], bf1[4][4];
#pragma unroll
            for (int mt = 0; mt < 4; mt++) ldsm_x4(af0[mt], aB[mt]);
#pragma unroll
            for (int nt = 0; nt < 4; nt++) ldsm_x4(bf0[nt], bB[nt]);

#pragma unroll 1
            for (int kk = 0; kk < 8; kk++) {
                // prefetch odd k-step
#pragma unroll
                for (int mt = 0; mt < 4; mt++) ldsm_x4(af1[mt], aB[mt] + 32);
#pragma unroll
                for (int nt = 0; nt < 4; nt++) ldsm_x4(bf1[nt], bB[nt] + 32);
                // compute even k-step
#pragma unroll
                for (int mt = 0; mt < 4; mt++)
#pragma unroll
                    for (int nt = 0; nt < 4; nt++) {
                        mma16816(acc[mt][2 * nt],     af0[mt], bf0[nt]);
                        mma16816(acc[mt][2 * nt + 1], af0[mt], bf0[nt] + 2);
                    }
                // prefetch next even k-step
                if (kk < 7) {
#pragma unroll
                    for (int mt = 0; mt < 4; mt++) ldsm_x4(af0[mt], aB[mt] + 64);
#pragma unroll
                    for (int nt = 0; nt < 4; nt++) ldsm_x4(bf0[nt], bB[nt] + 64);
                }
                // compute odd k-step
#pragma unroll
                for (int mt = 0; mt < 4; mt++)
#pragma unroll
                    for (int nt = 0; nt < 4; nt++) {
                        mma16816(acc[mt][2 * nt],     af1[mt], bf1[nt]);
                        mma16816(acc[mt][2 * nt + 1], af1[mt], bf1[nt] + 2);
                    }
#pragma unroll
                for (int mt = 0; mt < 4; mt++) aB[mt] += 64;
#pragma unroll
                for (int nt = 0; nt < 4; nt++) bB[nt] += 64;
            }
        }

        // ---- epilogue 2: +(b2+kind_emb), scatter to token rows ----
        {
            const float* b2k = g_bias2 + k * DMODEL;
#pragma unroll
            for (int mt = 0; mt < 4; mt++) {
                int r0 = m0w + mt * 16 + rA;
                int r1 = r0 + 8;
                int tok0 = s_tok[r0];
                int tok1 = s_tok[r1];
                float* o0 = out + (size_t)(tok0 < 0 ? 0 : tok0) * DMODEL;
                float* o1 = out + (size_t)(tok1 < 0 ? 0 : tok1) * DMODEL;
#pragma unroll
                for (int n8 = 0; n8 < 8; n8++) {
                    int col = n0w + n8 * 8 + cA;
                    float bi0 = b2k[col], bi1 = b2k[col + 1];
                    if (tok0 >= 0)
                        *reinterpret_cast<float2*>(o0 + col) =
                            make_float2(acc[mt][n8][0] + bi0, acc[mt][n8][1] + bi1);
                    if (tok1 >= 0)
                        *reinterpret_cast<float2*>(o1 + col) =
                            make_float2(acc[mt][n8][2] + bi0, acc[mt][n8][3] + bi1);
                }
            }
        }
    }
}

// ============================================================================
// kernel_launch — graph-capturable, allocation-free
// ============================================================================
extern "C" void kernel_launch(void* const* d_in, const int* in_sizes, int n_in,
                              void* d_out, int out_size) {
    const float* values = (const float*)d_in[0];
    const int*   kinds  = (const int*)d_in[1];
    const float* Bmat   = (const float*)d_in[2];
    const float* kemb   = (const float*)d_in[3];
    const float* W1     = (const float*)d_in[4];
    const float* b1     = (const float*)d_in[5];
    const float* W2     = (const float*)d_in[6];
    const float* b2     = (const float*)d_in[7];
    float* out = (float*)d_out;
    int T = in_sizes[1];

    static int n_sm = 0;
    if (!n_sm) {
        cudaFuncSetAttribute(fused_kernel, cudaFuncAttributeMaxDynamicSharedMemorySize, SMEM_BYTES);
        int dev = 0;
        cudaGetDevice(&dev);
        cudaDeviceGetAttribute(&n_sm, cudaDevAttrMultiProcessorCount, dev);
        if (n_sm <= 0) n_sm = 148;
    }

    int prep_elems = NKINDS * 256 * W2_KS;
    prep_kernel<<<(prep_elems + 255) / 256, 256>>>(W1, W2, b2, kemb);
    bucket_kernel<<<(T + 255) / 256, 256>>>(kinds, T);
    schedule_kernel<<<1, 32>>>();
    fused_kernel<<<n_sm, 256, SMEM_BYTES>>>(values, Bmat, b1, out);
}